// round 16
// baseline (speedup 1.0000x reference)
#include <cuda_runtime.h>

// ICFM v11: v4 dataflow + depth-2 per-warp register pipeline (ping-pong).
// Measured: v4 already runs at ~87% of the LTS practical cap (~6300 B/cyc)
// and ~90% of random-access DRAM ceiling; L2-policy (v10) was a no-op.
// Remaining loss is load duty-cycle: v4 waits on its gathers mid-iteration.
// Now: at iteration top, issue batch n+1's vec gathers (indices prefetched
// last iter) + batch n+2's index loads, then compute batch n from registers
// that have aged a full iteration. Manual 2x unroll = zero reg copies.

#define NSEG 16384
#define UNROLL 4   // slots; interactions per warp-batch = 2*UNROLL = 8
#define THREADS 128

__global__ void icfm_zero(float* __restrict__ out) {
    int i = blockIdx.x * blockDim.x + threadIdx.x;
    if (i < NSEG) out[i] = 0.0f;
}

__global__ void __launch_bounds__(THREADS) icfm_main(
    const int*    __restrict__ intr_idxs,
    const float*  __restrict__ intr_divs,
    const int2*   __restrict__ feat_idxs,
    const int*    __restrict__ seg_ids,
    const float4* __restrict__ vecs,     // [N_FEATS, 16] as float4
    const float*  __restrict__ intr_W,
    const float*  __restrict__ intr_b,
    float*        __restrict__ out,
    int T)
{
    const int lane  = threadIdx.x & 31;
    const int group = lane >> 4;      // which interaction of a slot-pair
    const int sub   = lane & 15;      // position within the 256B row
    const int oct   = lane & 7;       // interaction-in-batch this lane owns

    const int warp_global = (blockIdx.x * blockDim.x + threadIdx.x) >> 5;
    const int nwarps      = (gridDim.x * blockDim.x) >> 5;
    const int nbatches    = (T + 2 * UNROLL - 1) / (2 * UNROLL);

    const float bias = __ldg(&intr_b[0]);

    int b = warp_global;
    if (b >= nbatches) return;

    int2   fi[2][UNROLL];
    float4 va[2][UNROLL], vb[2][UNROLL];

    // --- prologue ---
    {   // indices for batch b
        const int base = b * (2 * UNROLL);
        #pragma unroll
        for (int it = 0; it < UNROLL; it++) {
            int j = base + it * 2 + group;
            fi[0][it] = __ldg(&feat_idxs[j < T ? j : T - 1]);
        }
    }
    #pragma unroll
    for (int it = 0; it < UNROLL; it++) {   // gathers for batch b
        va[0][it] = __ldg(&vecs[(long long)fi[0][it].x * 16 + sub]);
        vb[0][it] = __ldg(&vecs[(long long)fi[0][it].y * 16 + sub]);
    }
    {   // indices for batch b+nwarps (clamped)
        int bn = b + nwarps; if (bn > nbatches - 1) bn = nbatches - 1;
        const int base = bn * (2 * UNROLL);
        #pragma unroll
        for (int it = 0; it < UNROLL; it++) {
            int j = base + it * 2 + group;
            fi[1][it] = __ldg(&feat_idxs[j < T ? j : T - 1]);
        }
    }

    // --- main loop, manual 2x unroll; parity pp indexes the ping-pong regs ---
    while (b < nbatches) {
        #pragma unroll
        for (int pp = 0; pp < 2; pp++) {
            if (b >= nbatches) break;
            const int np = pp ^ 1;

            // 1. Issue next batch's 8 vec gathers (indices aged one iteration).
            #pragma unroll
            for (int it = 0; it < UNROLL; it++) {
                va[np][it] = __ldg(&vecs[(long long)fi[np][it].x * 16 + sub]);
                vb[np][it] = __ldg(&vecs[(long long)fi[np][it].y * 16 + sub]);
            }

            // 2. Issue batch b+2*nwarps index loads (clamped) into fi[pp].
            {
                int b2 = b + 2 * nwarps; if (b2 > nbatches - 1) b2 = nbatches - 1;
                const int base2 = b2 * (2 * UNROLL);
                #pragma unroll
                for (int it = 0; it < UNROLL; it++) {
                    int j = base2 + it * 2 + group;
                    fi[pp][it] = __ldg(&feat_idxs[j < T ? j : T - 1]);
                }
            }

            // 3. Scalars for current batch b.
            const int  base   = b * (2 * UNROLL);
            const int  j2     = base + oct;
            const bool valid2 = j2 < T;
            const int  j2c    = valid2 ? j2 : T - 1;
            const int  idx    = __ldg(&intr_idxs[j2c]);
            const float dv    = __ldg(&intr_divs[j2c]);
            const int  sg     = __ldg(&seg_ids[j2c]);
            const float w     = __ldg(&intr_W[idx]);
            const float coef  = __fdividef(w, dv);

            // 4. Compute batch b from va[pp]/vb[pp] (aged one full iteration).
            float v = 0.0f;
            #pragma unroll
            for (int it = 0; it < UNROLL; it++) {
                float p = va[pp][it].x * vb[pp][it].x + va[pp][it].y * vb[pp][it].y
                        + va[pp][it].z * vb[pp][it].z + va[pp][it].w * vb[pp][it].w;
                p += __shfl_xor_sync(0xffffffffu, p, 8);
                p += __shfl_xor_sync(0xffffffffu, p, 4);
                p += __shfl_xor_sync(0xffffffffu, p, 2);
                p += __shfl_xor_sync(0xffffffffu, p, 1);
                const float q  = __shfl_xor_sync(0xffffffffu, p, 16);
                const float g0 = (lane < 16) ? p : q;
                const float g1 = (lane < 16) ? q : p;
                if ((lane & 6) == 2 * it)
                    v = (lane & 1) ? g1 : g0;
            }
            v = valid2 ? (coef * v + bias) : 0.0f;

            // 5. Segment-aggregated accumulate.
            const int      sg0 = __shfl_sync(0xffffffffu, sg, 0);
            const unsigned uni = __ballot_sync(0xffffffffu, sg == sg0);
            if (uni == 0xffffffffu) {
                v += __shfl_xor_sync(0xffffffffu, v, 4);
                v += __shfl_xor_sync(0xffffffffu, v, 2);
                v += __shfl_xor_sync(0xffffffffu, v, 1);
                if (lane == 0) atomicAdd(&out[sg0], v);
            } else {
                if (lane < 8) atomicAdd(&out[sg], v);
            }

            b += nwarps;
        }
    }
}

extern "C" void kernel_launch(void* const* d_in, const int* in_sizes, int n_in,
                              void* d_out, int out_size) {
    const int*    intr_idxs = (const int*)   d_in[0];
    const float*  intr_divs = (const float*) d_in[1];
    const int2*   feat_idxs = (const int2*)  d_in[2];
    const int*    seg_ids   = (const int*)   d_in[3];
    const float4* vecs      = (const float4*)d_in[4];
    const float*  intr_W    = (const float*) d_in[5];
    const float*  intr_b    = (const float*) d_in[6];
    float*        out       = (float*)d_out;

    const int T = in_sizes[0];

    icfm_zero<<<(NSEG + 255) / 256, 256>>>(out);

    // Full-residency persistent grid (pure host-side query; capture-safe).
    int cta_per_sm = 0;
    cudaOccupancyMaxActiveBlocksPerMultiprocessor(&cta_per_sm, icfm_main,
                                                  THREADS, 0);
    if (cta_per_sm < 1) cta_per_sm = 4;
    const int blocks = 148 * cta_per_sm;
    icfm_main<<<blocks, THREADS>>>(intr_idxs, intr_divs, feat_idxs, seg_ids,
                                   vecs, intr_W, intr_b, out, T);
}

// round 17
// speedup vs baseline: 1.3478x; 1.3478x over previous
#include <cuda_runtime.h>

// ICFM v12: exact v4 dataflow (best: 54us) with 128-thread blocks.
// Six structural experiments (L2 prefetch, reg-cap occupancy, cp.async
// staging, redux, serialized butterfly, depth-2 reg pipeline) all regressed:
// v4 is ~87% of the measured LTS cap (~6300 B/cyc) and ~90% of the random
// 256B DRAM ceiling. Last free knob: reg-file granularity. 56 regs at
// 128-thr blocks quantizes to 9 CTAs/SM (36 warps, 56% occ) vs 4 CTAs
// (32 warps, 50%) at 256 — no reg cap, no spills, +12.5% resident warps.

#define NSEG 16384
#define UNROLL 4   // slots; interactions per warp-batch = 2*UNROLL = 8
#define THREADS 128

__global__ void icfm_zero(float* __restrict__ out) {
    int i = blockIdx.x * blockDim.x + threadIdx.x;
    if (i < NSEG) out[i] = 0.0f;
}

__global__ void __launch_bounds__(THREADS) icfm_main(
    const int*    __restrict__ intr_idxs,
    const float*  __restrict__ intr_divs,
    const int2*   __restrict__ feat_idxs,
    const int*    __restrict__ seg_ids,
    const float4* __restrict__ vecs,     // [N_FEATS, 16] as float4
    const float*  __restrict__ intr_W,
    const float*  __restrict__ intr_b,
    float*        __restrict__ out,
    int T)
{
    const int lane  = threadIdx.x & 31;
    const int group = lane >> 4;      // which interaction of a slot-pair
    const int sub   = lane & 15;      // position within the 256B row
    const int oct   = lane & 7;       // interaction-in-batch this lane owns

    const int warp_global = (blockIdx.x * blockDim.x + threadIdx.x) >> 5;
    const int nwarps      = (gridDim.x * blockDim.x) >> 5;
    const int nbatches    = (T + 2 * UNROLL - 1) / (2 * UNROLL);

    const float bias = __ldg(&intr_b[0]);

    int batch = warp_global;
    if (batch >= nbatches) return;

    // Prologue: feat indices for the first batch (clamped).
    int2 fc[UNROLL];
    {
        const int base = batch * (2 * UNROLL);
        #pragma unroll
        for (int it = 0; it < UNROLL; it++) {
            int j = base + it * 2 + group;
            fc[it] = __ldg(&feat_idxs[j < T ? j : T - 1]);
        }
    }

    while (batch < nbatches) {
        const int base = batch * (2 * UNROLL);
        const int nb   = batch + nwarps;

        // 8 independent row gathers (MLP=8), issued first.
        float4 a[UNROLL], b[UNROLL];
        #pragma unroll
        for (int it = 0; it < UNROLL; it++) {
            a[it] = __ldg(&vecs[(long long)fc[it].x * 16 + sub]);
            b[it] = __ldg(&vecs[(long long)fc[it].y * 16 + sub]);
        }

        // Lane-parallel scalar loads for this batch (overlap the gather wait).
        const int  j2     = base + oct;
        const bool valid2 = j2 < T;
        const int  j2c    = valid2 ? j2 : T - 1;
        const int  idx    = __ldg(&intr_idxs[j2c]);
        const float dv    = __ldg(&intr_divs[j2c]);
        const int  sg     = __ldg(&seg_ids[j2c]);
        const float w     = __ldg(&intr_W[idx]);
        const float coef  = __fdividef(w, dv);

        // Prefetch next batch's feat indices (registers only).
        int2 fn[UNROLL];
        if (nb < nbatches) {
            const int nbase = nb * (2 * UNROLL);
            #pragma unroll
            for (int it = 0; it < UNROLL; it++) {
                int j = nbase + it * 2 + group;
                fn[it] = __ldg(&feat_idxs[j < T ? j : T - 1]);
            }
        }

        // Dot products + 16-lane reductions (4 independent trees — keep ILP).
        float v = 0.0f;
        #pragma unroll
        for (int it = 0; it < UNROLL; it++) {
            float p = a[it].x * b[it].x + a[it].y * b[it].y
                    + a[it].z * b[it].z + a[it].w * b[it].w;
            p += __shfl_xor_sync(0xffffffffu, p, 8);
            p += __shfl_xor_sync(0xffffffffu, p, 4);
            p += __shfl_xor_sync(0xffffffffu, p, 2);
            p += __shfl_xor_sync(0xffffffffu, p, 1);
            const float q  = __shfl_xor_sync(0xffffffffu, p, 16);
            const float g0 = (lane < 16) ? p : q;
            const float g1 = (lane < 16) ? q : p;
            if ((lane & 6) == 2 * it)
                v = (lane & 1) ? g1 : g0;
        }
        v = valid2 ? (coef * v + bias) : 0.0f;

        // Segment-aggregated accumulate: one atomic when the batch is uniform.
        const int      sg0 = __shfl_sync(0xffffffffu, sg, 0);
        const unsigned uni = __ballot_sync(0xffffffffu, sg == sg0);
        if (uni == 0xffffffffu) {
            v += __shfl_xor_sync(0xffffffffu, v, 4);
            v += __shfl_xor_sync(0xffffffffu, v, 2);
            v += __shfl_xor_sync(0xffffffffu, v, 1);
            if (lane == 0) atomicAdd(&out[sg0], v);
        } else {
            if (lane < 8) atomicAdd(&out[sg], v);
        }

        #pragma unroll
        for (int it = 0; it < UNROLL; it++) fc[it] = fn[it];
        batch = nb;
    }
}

extern "C" void kernel_launch(void* const* d_in, const int* in_sizes, int n_in,
                              void* d_out, int out_size) {
    const int*    intr_idxs = (const int*)   d_in[0];
    const float*  intr_divs = (const float*) d_in[1];
    const int2*   feat_idxs = (const int2*)  d_in[2];
    const int*    seg_ids   = (const int*)   d_in[3];
    const float4* vecs      = (const float4*)d_in[4];
    const float*  intr_W    = (const float*) d_in[5];
    const float*  intr_b    = (const float*) d_in[6];
    float*        out       = (float*)d_out;

    const int T = in_sizes[0];

    icfm_zero<<<(NSEG + 255) / 256, 256>>>(out);

    // Full-residency persistent grid (pure host-side query; capture-safe).
    int cta_per_sm = 0;
    cudaOccupancyMaxActiveBlocksPerMultiprocessor(&cta_per_sm, icfm_main,
                                                  THREADS, 0);
    if (cta_per_sm < 1) cta_per_sm = 8;
    const int blocks = 148 * cta_per_sm;
    icfm_main<<<blocks, THREADS>>>(intr_idxs, intr_divs, feat_idxs, seg_ids,
                                   vecs, intr_W, intr_b, out, T);
}